// round 9
// baseline (speedup 1.0000x reference)
#include <cuda_runtime.h>
#include <math.h>
#include <stdint.h>

#define Bsz 256
#define Tsz 512
#define Dsz 256
#define Ksz 256

__device__ float g_xU[Bsz * Tsz * Ksz];   // 128 MB scratch for xU = x@U + b

// ===========================================================================
// Helpers
// ===========================================================================
__device__ __forceinline__ unsigned long long pack2(float lo, float hi) {
    unsigned long long r;
    asm("mov.b64 %0, {%1, %2};" : "=l"(r) : "f"(lo), "f"(hi));
    return r;
}
__device__ __forceinline__ void unpack2(unsigned long long v, float& lo, float& hi) {
    asm("mov.b64 {%0, %1}, %2;" : "=f"(lo), "=f"(hi) : "l"(v));
}
__device__ __forceinline__ void fma2(unsigned long long& acc, unsigned long long h, unsigned long long w) {
    asm("fma.rn.f32x2 %0, %1, %2, %0;" : "+l"(acc) : "l"(h), "l"(w));
}
__device__ __forceinline__ uint32_t f2tf32(float f) {
    uint32_t r;
    asm("cvt.rna.tf32.f32 %0, %1;" : "=r"(r) : "f"(f));
    return r;
}
__device__ __forceinline__ void mma_tf32(float* c, const uint32_t* a, const uint32_t* b) {
    asm("mma.sync.aligned.m16n8k8.row.col.f32.tf32.tf32.f32 "
        "{%0,%1,%2,%3}, {%4,%5,%6,%7}, {%8,%9}, {%0,%1,%2,%3};"
        : "+f"(c[0]), "+f"(c[1]), "+f"(c[2]), "+f"(c[3])
        : "r"(a[0]), "r"(a[1]), "r"(a[2]), "r"(a[3]), "r"(b[0]), "r"(b[1]));
}
__device__ __forceinline__ uint32_t smem_u32(const void* p) {
    uint32_t a;
    asm("{ .reg .u64 t; cvta.to.shared.u64 t, %1; cvt.u32.u64 %0, t; }" : "=r"(a) : "l"(p));
    return a;
}

// ===========================================================================
// Kernel A: xU = X @ U + b   — tf32 tensor cores (unchanged)
// ===========================================================================
__global__ void __launch_bounds__(256) gemm_xu_tc(
    const float* __restrict__ X,
    const float* __restrict__ U,
    const float* __restrict__ bias,
    float* __restrict__ out)
{
    __shared__ float As[128][36];
    __shared__ float Bs[32][132];

    const int tid  = threadIdx.x;
    const int wid  = tid >> 5;
    const int lane = tid & 31;
    const int wm   = (wid & 3) * 32;
    const int wn   = (wid >> 2) * 64;
    const int row0 = blockIdx.y * 128;
    const int col0 = blockIdx.x * 128;

    float acc[2][8][4];
    #pragma unroll
    for (int mt = 0; mt < 2; mt++)
        #pragma unroll
        for (int nt = 0; nt < 8; nt++)
            #pragma unroll
            for (int i = 0; i < 4; i++) acc[mt][nt][i] = 0.0f;

    const int ar = lane >> 2;
    const int ac = lane & 3;
    const int bk = lane & 3;
    const int bn = lane >> 2;

    for (int kb = 0; kb < Dsz; kb += 32) {
        #pragma unroll
        for (int i = 0; i < 4; i++) {
            int lin = tid + i * 256;
            int m = lin >> 3, k = (lin & 7) << 2;
            float4 v = *(const float4*)&X[(size_t)(row0 + m) * Dsz + kb + k];
            v.x = __uint_as_float(f2tf32(v.x));
            v.y = __uint_as_float(f2tf32(v.y));
            v.z = __uint_as_float(f2tf32(v.z));
            v.w = __uint_as_float(f2tf32(v.w));
            *(float4*)&As[m][k] = v;

            int k2 = lin >> 5, n = (lin & 31) << 2;
            float4 u = *(const float4*)&U[(size_t)(kb + k2) * Ksz + col0 + n];
            u.x = __uint_as_float(f2tf32(u.x));
            u.y = __uint_as_float(f2tf32(u.y));
            u.z = __uint_as_float(f2tf32(u.z));
            u.w = __uint_as_float(f2tf32(u.w));
            *(float4*)&Bs[k2][n] = u;
        }
        __syncthreads();

        #pragma unroll
        for (int kc = 0; kc < 4; kc++) {
            const int k0 = kc * 8;
            uint32_t af[2][4];
            #pragma unroll
            for (int mt = 0; mt < 2; mt++) {
                const int mb = wm + mt * 16;
                af[mt][0] = __float_as_uint(As[mb + ar    ][k0 + ac    ]);
                af[mt][1] = __float_as_uint(As[mb + ar + 8][k0 + ac    ]);
                af[mt][2] = __float_as_uint(As[mb + ar    ][k0 + ac + 4]);
                af[mt][3] = __float_as_uint(As[mb + ar + 8][k0 + ac + 4]);
            }
            #pragma unroll
            for (int nt = 0; nt < 8; nt++) {
                uint32_t bf[2];
                const int nb = wn + nt * 8 + bn;
                bf[0] = __float_as_uint(Bs[k0 + bk    ][nb]);
                bf[1] = __float_as_uint(Bs[k0 + bk + 4][nb]);
                mma_tf32(acc[0][nt], af[0], bf);
                mma_tf32(acc[1][nt], af[1], bf);
            }
        }
        __syncthreads();
    }

    #pragma unroll
    for (int nt = 0; nt < 8; nt++) {
        const int cb = col0 + wn + nt * 8 + 2 * (lane & 3);
        float2 bb = *(const float2*)&bias[cb];
        #pragma unroll
        for (int mt = 0; mt < 2; mt++) {
            const int r = row0 + wm + mt * 16 + (lane >> 2);
            float2 o0 = { acc[mt][nt][0] + bb.x, acc[mt][nt][1] + bb.y };
            float2 o1 = { acc[mt][nt][2] + bb.x, acc[mt][nt][3] + bb.y };
            *(float2*)&out[(size_t)r       * Ksz + cb] = o0;
            *(float2*)&out[(size_t)(r + 8) * Ksz + cb] = o1;
        }
    }
}

// ===========================================================================
// Kernel B (R9): recurrence. 64 clusters x 2 CTAs x 512 threads.
// Full column coverage: warp wid (0..15), c = wid*8 + lane>>2 in 0..127,
// q = lane&3 (d-quarter, 64 d each), 4 batch rows per thread.
// shfl-only q-reduction; warp-aggregated remote mbarrier arrive (lane 0,
// count=8; init = 16 warps x 8 = 128). One __syncthreads per step.
// ===========================================================================
__global__ void __launch_bounds__(512, 1) __cluster_dims__(2, 1, 1)
rnn_rec9_kernel(const float* __restrict__ xU,
                const float* __restrict__ W,
                float* __restrict__ out)
{
    __shared__ alignas(16) float hb[2][4][Ksz];   // [buf][row][d] = 8 KB
    __shared__ unsigned long long mbar[2];        // [buf]

    const int tid  = threadIdx.x;
    const int wid  = tid >> 5;                  // 0..15
    const int lane = tid & 31;
    const int q    = lane & 3;                  // d-quarter
    const int c    = wid * 8 + (lane >> 2);     // column within CTA half 0..127

    uint32_t rank;
    asm("mov.u32 %0, %%cluster_ctarank;" : "=r"(rank));
    const uint32_t peer = rank ^ 1u;
    const int cg = ((int)rank << 7) + c;        // global column 0..255
    const int b0 = (blockIdx.x >> 1) * 4;       // 4 batch rows per cluster

    // W slice, pre-packed: Wp[i] = (W[64q+2i][cg], W[64q+2i+1][cg])
    unsigned long long Wp[32];
    #pragma unroll
    for (int i = 0; i < 32; i++) {
        float w0 = W[(size_t)(q * 64 + 2 * i    ) * Ksz + cg];
        float w1 = W[(size_t)(q * 64 + 2 * i + 1) * Ksz + cg];
        Wp[i] = pack2(w0, w1);
    }

    // zero h buffers; init mbarriers: 16 warps x count 8 = 128 arrivals/phase
    for (int i = tid; i < 2 * 4 * Ksz; i += 512) ((float*)hb)[i] = 0.0f;
    if (tid == 0) {
        #pragma unroll
        for (int p = 0; p < 2; p++) {
            uint32_t m = smem_u32(&mbar[p]);
            asm volatile("mbarrier.init.shared.b64 [%0], %1;" :: "r"(m), "r"(128) : "memory");
        }
    }
    __syncthreads();
    asm volatile("barrier.cluster.arrive.aligned;" ::: "memory");
    asm volatile("barrier.cluster.wait.aligned;"   ::: "memory");

    uint32_t mbL[2], mbP[2];
    #pragma unroll
    for (int p = 0; p < 2; p++) {
        mbL[p] = smem_u32(&mbar[p]);
        asm("mapa.shared::cluster.u32 %0, %1, %2;" : "=r"(mbP[p]) : "r"(mbL[p]), "r"(peer));
    }
    // h write base (row 0 of column cg); rows at +1024-byte steps
    uint32_t wrL[2], wrP[2];
    #pragma unroll
    for (int p = 0; p < 2; p++) {
        uint32_t a = smem_u32(&hb[p][0][cg]);
        wrL[p] = a;
        asm("mapa.shared::cluster.u32 %0, %1, %2;" : "=r"(wrP[p]) : "r"(a), "r"(peer));
    }

    const float* xp0 = xU + (size_t)(b0 + 0) * Tsz * Ksz + cg;
    const float* xp1 = xU + (size_t)(b0 + 1) * Tsz * Ksz + cg;
    const float* xp2 = xU + (size_t)(b0 + 2) * Tsz * Ksz + cg;
    const float* xp3 = xU + (size_t)(b0 + 3) * Tsz * Ksz + cg;
    float xu0 = 0.f, xu1 = 0.f, xu2 = 0.f, xu3 = 0.f;
    if (q == 0) { xu0 = xp0[0]; xu1 = xp1[0]; xu2 = xp2[0]; xu3 = xp3[0]; }

    float hv0 = 0.f, hv1 = 0.f, hv2 = 0.f, hv3 = 0.f;
    int ph[2] = {0, 0};

    for (int t = 0; t < Tsz; t++) {
        const int buf = t & 1;
        if (t) {
            uint32_t mb = mbL[buf];
            int phase = ph[buf];
            ph[buf] ^= 1;
            asm volatile(
                "{\n\t"
                ".reg .pred P;\n\t"
                "WL_%=:\n\t"
                "mbarrier.try_wait.parity.acquire.cluster.shared::cta.b64 P, [%0], %1, 0x989680;\n\t"
                "@P bra.uni WD_%=;\n\t"
                "bra.uni WL_%=;\n\t"
                "WD_%=:\n\t"
                "}"
                :: "r"(mb), "r"(phase) : "memory");
        }

        // 4 accumulation chains (rows), 32 iters x (4 LDS.64 + 4 FMA2)
        const double* h0 = (const double*)&hb[buf][0][q * 64];
        const double* h1 = (const double*)&hb[buf][1][q * 64];
        const double* h2 = (const double*)&hb[buf][2][q * 64];
        const double* h3 = (const double*)&hb[buf][3][q * 64];
        unsigned long long a0 = pack2(0.f, 0.f);
        unsigned long long a1 = a0, a2 = a0, a3 = a0;
        #pragma unroll
        for (int i = 0; i < 32; i++) {
            fma2(a0, __double_as_longlong(h0[i]), Wp[i]);
            fma2(a1, __double_as_longlong(h1[i]), Wp[i]);
            fma2(a2, __double_as_longlong(h2[i]), Wp[i]);
            fma2(a3, __double_as_longlong(h3[i]), Wp[i]);
        }

        // fold d-parity, then shfl-reduce over q (lane bits 0-1)
        float e, o;
        unpack2(a0, e, o); float s0 = e + o;
        unpack2(a1, e, o); float s1 = e + o;
        unpack2(a2, e, o); float s2 = e + o;
        unpack2(a3, e, o); float s3 = e + o;
        s0 += __shfl_xor_sync(0xffffffffu, s0, 1);
        s1 += __shfl_xor_sync(0xffffffffu, s1, 1);
        s2 += __shfl_xor_sync(0xffffffffu, s2, 1);
        s3 += __shfl_xor_sync(0xffffffffu, s3, 1);
        s0 += __shfl_xor_sync(0xffffffffu, s0, 2);
        s1 += __shfl_xor_sync(0xffffffffu, s1, 2);
        s2 += __shfl_xor_sync(0xffffffffu, s2, 2);
        s3 += __shfl_xor_sync(0xffffffffu, s3, 2);

        const int wr = (t + 1 < Tsz);
        const int p  = (t + 1) & 1;
        if (q == 0) {
            s0 += xu0; s1 += xu1; s2 += xu2; s3 += xu3;
            {
                int tn = wr ? t + 1 : t;
                size_t off = (size_t)tn * Ksz;
                xu0 = xp0[off]; xu1 = xp1[off]; xu2 = xp2[off]; xu3 = xp3[off];
            }
            hv0 = tanhf(s0); hv1 = tanhf(s1); hv2 = tanhf(s2); hv3 = tanhf(s3);

            if (wr) {
                asm volatile(
                    "st.shared.f32 [%0], %1; st.shared.f32 [%0+1024], %2;"
                    "st.shared.f32 [%0+2048], %3; st.shared.f32 [%0+3072], %4;"
                    :: "r"(wrL[p]), "f"(hv0), "f"(hv1), "f"(hv2), "f"(hv3) : "memory");
                asm volatile(
                    "st.shared::cluster.f32 [%0], %1; st.shared::cluster.f32 [%0+1024], %2;"
                    "st.shared::cluster.f32 [%0+2048], %3; st.shared::cluster.f32 [%0+3072], %4;"
                    :: "r"(wrP[p]), "f"(hv0), "f"(hv1), "f"(hv2), "f"(hv3) : "memory");
            }
        }
        // warp-aggregated remote arrive: signals (a) this warp finished reading
        // buf, (b) its q0 lanes' h stores are ordered-before (release)
        __syncwarp();
        if (wr && lane == 0) {
            asm volatile("mbarrier.arrive.release.cluster.shared::cluster.b64 _, [%0], %1;"
                         :: "r"(mbP[p]), "r"(8) : "memory");
        }
        __syncthreads();   // local h stores visible CTA-wide
    }

    if (q == 0) {
        out[(size_t)(b0 + 0) * Ksz + cg] = hv0;
        out[(size_t)(b0 + 1) * Ksz + cg] = hv1;
        out[(size_t)(b0 + 2) * Ksz + cg] = hv2;
        out[(size_t)(b0 + 3) * Ksz + cg] = hv3;
    }
}

// ===========================================================================
// Launch
// ===========================================================================
extern "C" void kernel_launch(void* const* d_in, const int* in_sizes, int n_in,
                              void* d_out, int out_size)
{
    const float* x    = (const float*)d_in[0];   // [256, 512, 256]
    const float* U    = (const float*)d_in[1];   // [256, 256]
    const float* W    = (const float*)d_in[2];   // [256, 256]
    const float* bias = (const float*)d_in[3];   // [256]
    float* out        = (float*)d_out;           // [256, 1, 256]

    float* xU;
    cudaGetSymbolAddress((void**)&xU, g_xU);

    dim3 gridA(Ksz / 128, (Bsz * Tsz) / 128);    // (2, 1024)
    gemm_xu_tc<<<gridA, 256>>>(x, U, bias, xU);

    rnn_rec9_kernel<<<(Bsz / 4) * 2, 512>>>(xU, W, out);
}

// round 11
// speedup vs baseline: 3.6620x; 3.6620x over previous
#include <cuda_runtime.h>
#include <math.h>
#include <stdint.h>

#define Bsz 256
#define Tsz 512
#define Dsz 256
#define Ksz 256

__device__ float g_xU[Bsz * Tsz * Ksz];   // 128 MB scratch for xU = x@U + b

// ===========================================================================
// Helpers
// ===========================================================================
__device__ __forceinline__ unsigned long long pack2(float lo, float hi) {
    unsigned long long r;
    asm("mov.b64 %0, {%1, %2};" : "=l"(r) : "f"(lo), "f"(hi));
    return r;
}
__device__ __forceinline__ void unpack2(unsigned long long v, float& lo, float& hi) {
    asm("mov.b64 {%0, %1}, %2;" : "=f"(lo), "=f"(hi) : "l"(v));
}
__device__ __forceinline__ void fma2(unsigned long long& acc, unsigned long long h, unsigned long long w) {
    asm("fma.rn.f32x2 %0, %1, %2, %0;" : "+l"(acc) : "l"(h), "l"(w));
}
__device__ __forceinline__ void add2(unsigned long long& a, unsigned long long b) {
    asm("add.rn.f32x2 %0, %0, %1;" : "+l"(a) : "l"(b));
}
__device__ __forceinline__ uint32_t f2tf32(float f) {
    uint32_t r;
    asm("cvt.rna.tf32.f32 %0, %1;" : "=r"(r) : "f"(f));
    return r;
}
__device__ __forceinline__ void mma_tf32(float* c, const uint32_t* a, const uint32_t* b) {
    asm("mma.sync.aligned.m16n8k8.row.col.f32.tf32.tf32.f32 "
        "{%0,%1,%2,%3}, {%4,%5,%6,%7}, {%8,%9}, {%0,%1,%2,%3};"
        : "+f"(c[0]), "+f"(c[1]), "+f"(c[2]), "+f"(c[3])
        : "r"(a[0]), "r"(a[1]), "r"(a[2]), "r"(a[3]), "r"(b[0]), "r"(b[1]));
}
__device__ __forceinline__ uint32_t smem_u32(const void* p) {
    uint32_t a;
    asm("{ .reg .u64 t; cvta.to.shared.u64 t, %1; cvt.u32.u64 %0, t; }" : "=r"(a) : "l"(p));
    return a;
}

// ===========================================================================
// Kernel A: xU = X @ U + b   — tf32 tensor cores (unchanged)
// ===========================================================================
__global__ void __launch_bounds__(256) gemm_xu_tc(
    const float* __restrict__ X,
    const float* __restrict__ U,
    const float* __restrict__ bias,
    float* __restrict__ out)
{
    __shared__ float As[128][36];
    __shared__ float Bs[32][132];

    const int tid  = threadIdx.x;
    const int wid  = tid >> 5;
    const int lane = tid & 31;
    const int wm   = (wid & 3) * 32;
    const int wn   = (wid >> 2) * 64;
    const int row0 = blockIdx.y * 128;
    const int col0 = blockIdx.x * 128;

    float acc[2][8][4];
    #pragma unroll
    for (int mt = 0; mt < 2; mt++)
        #pragma unroll
        for (int nt = 0; nt < 8; nt++)
            #pragma unroll
            for (int i = 0; i < 4; i++) acc[mt][nt][i] = 0.0f;

    const int ar = lane >> 2;
    const int ac = lane & 3;
    const int bk = lane & 3;
    const int bn = lane >> 2;

    for (int kb = 0; kb < Dsz; kb += 32) {
        #pragma unroll
        for (int i = 0; i < 4; i++) {
            int lin = tid + i * 256;
            int m = lin >> 3, k = (lin & 7) << 2;
            float4 v = *(const float4*)&X[(size_t)(row0 + m) * Dsz + kb + k];
            v.x = __uint_as_float(f2tf32(v.x));
            v.y = __uint_as_float(f2tf32(v.y));
            v.z = __uint_as_float(f2tf32(v.z));
            v.w = __uint_as_float(f2tf32(v.w));
            *(float4*)&As[m][k] = v;

            int k2 = lin >> 5, n = (lin & 31) << 2;
            float4 u = *(const float4*)&U[(size_t)(kb + k2) * Ksz + col0 + n];
            u.x = __uint_as_float(f2tf32(u.x));
            u.y = __uint_as_float(f2tf32(u.y));
            u.z = __uint_as_float(f2tf32(u.z));
            u.w = __uint_as_float(f2tf32(u.w));
            *(float4*)&Bs[k2][n] = u;
        }
        __syncthreads();

        #pragma unroll
        for (int kc = 0; kc < 4; kc++) {
            const int k0 = kc * 8;
            uint32_t af[2][4];
            #pragma unroll
            for (int mt = 0; mt < 2; mt++) {
                const int mb = wm + mt * 16;
                af[mt][0] = __float_as_uint(As[mb + ar    ][k0 + ac    ]);
                af[mt][1] = __float_as_uint(As[mb + ar + 8][k0 + ac    ]);
                af[mt][2] = __float_as_uint(As[mb + ar    ][k0 + ac + 4]);
                af[mt][3] = __float_as_uint(As[mb + ar + 8][k0 + ac + 4]);
            }
            #pragma unroll
            for (int nt = 0; nt < 8; nt++) {
                uint32_t bf[2];
                const int nb = wn + nt * 8 + bn;
                bf[0] = __float_as_uint(Bs[k0 + bk    ][nb]);
                bf[1] = __float_as_uint(Bs[k0 + bk + 4][nb]);
                mma_tf32(acc[0][nt], af[0], bf);
                mma_tf32(acc[1][nt], af[1], bf);
            }
        }
        __syncthreads();
    }

    #pragma unroll
    for (int nt = 0; nt < 8; nt++) {
        const int cb = col0 + wn + nt * 8 + 2 * (lane & 3);
        float2 bb = *(const float2*)&bias[cb];
        #pragma unroll
        for (int mt = 0; mt < 2; mt++) {
            const int r = row0 + wm + mt * 16 + (lane >> 2);
            float2 o0 = { acc[mt][nt][0] + bb.x, acc[mt][nt][1] + bb.y };
            float2 o1 = { acc[mt][nt][2] + bb.x, acc[mt][nt][3] + bb.y };
            *(float2*)&out[(size_t)r       * Ksz + cb] = o0;
            *(float2*)&out[(size_t)(r + 8) * Ksz + cb] = o1;
        }
    }
}

// ===========================================================================
// Kernel B (R11): recurrence. 32 clusters x 4 CTAs x 512 threads; 8 rows/cluster.
// CTA rank owns output columns [64*rank, 64*rank+64) with the FULL d=256 dot
// product (W slice in registers, 32/thread) -> NO cross-CTA reduction.
// Cross-CTA traffic = h broadcast only: plain st.shared::cluster + ONE full
// barrier.cluster per step (the only sync pattern with measured passes here).
// Thread map: lane = dg*4 + cl; dg = d-group (32 d), col c = warp*4 + cl.
// h layout: [buf][row][dg-chunk of 36 floats] -> LDS.128 conflict-free
// (lane dg hits banks 4(dg+i) mod 32, disjoint for all i).
// Reduction over dg = 3 shfl.bfly rounds; lane dg then owns (row=dg, col=c).
// ===========================================================================
#define HROW 288                    // floats per row: 8 chunks * 36
#define HBUF (8 * HROW)             // 2304 floats per buffer

__global__ void __launch_bounds__(512, 1) __cluster_dims__(4, 1, 1)
rnn_rec11_kernel(const float* __restrict__ xU,
                 const float* __restrict__ W,
                 float* __restrict__ out)
{
    __shared__ alignas(16) float hb[2][HBUF];   // 18.4 KB

    const int tid  = threadIdx.x;
    const int w    = tid >> 5;                  // 0..15
    const int lane = tid & 31;
    const int dg   = lane >> 2;                 // d-group 0..7 (32 d each)
    const int cl   = lane & 3;
    const int c    = w * 4 + cl;                // column within CTA 0..63

    uint32_t rank;
    asm("mov.u32 %0, %%cluster_ctarank;" : "=r"(rank));
    const int cg = (int)rank * 64 + c;          // global column 0..255
    const int b0 = (blockIdx.x >> 2) * 8;       // 8 batch rows per cluster

    // W slice: Wp[i] = (W[32dg+2i][cg], W[32dg+2i+1][cg]), i<16
    unsigned long long Wp[16];
    #pragma unroll
    for (int i = 0; i < 16; i++) {
        float w0 = W[(size_t)(dg * 32 + 2 * i    ) * Ksz + cg];
        float w1 = W[(size_t)(dg * 32 + 2 * i + 1) * Ksz + cg];
        Wp[i] = pack2(w0, w1);
    }

    // zero h buffers
    for (int i = tid; i < 2 * HBUF; i += 512) ((float*)hb)[i] = 0.0f;
    __syncthreads();
    asm volatile("barrier.cluster.arrive.aligned;" ::: "memory");
    asm volatile("barrier.cluster.wait.aligned;"   ::: "memory");

    // h write addresses: local + 3 peers (row = dg, position = cg)
    const int wroff = (dg * HROW + (cg >> 5) * 36 + (cg & 31)) * 4;
    uint32_t wrL[2], wrP[3][2];
    #pragma unroll
    for (int p = 0; p < 2; p++) wrL[p] = smem_u32(&hb[p][0]) + wroff;
    #pragma unroll
    for (int k = 0; k < 3; k++) {
        uint32_t rk = (rank + 1 + k) & 3;
        #pragma unroll
        for (int p = 0; p < 2; p++)
            asm("mapa.shared::cluster.u32 %0, %1, %2;" : "=r"(wrP[k][p]) : "r"(wrL[p]), "r"(rk));
    }

    // xu pointer: row b0+dg, column cg
    const float* xp = xU + (size_t)(b0 + dg) * Tsz * Ksz + cg;
    float xu = xp[0];
    float hv = 0.0f;

    for (int t = 0; t < Tsz; t++) {
        const int buf = t & 1;

        // 16 interleaved chains: rows 0..7 x even/odd-d. 64 LDS.128 + 128 FMA2.
        const char* hbase = (const char*)&hb[buf][0] + dg * 144;
        unsigned long long A[8], Bc[8];
        #pragma unroll
        for (int r = 0; r < 8; r++) { A[r] = 0ull; Bc[r] = 0ull; }
        #pragma unroll
        for (int i = 0; i < 8; i++) {
            #pragma unroll
            for (int r = 0; r < 8; r++) {
                double2 v = *(const double2*)(hbase + r * (HROW * 4) + i * 16);
                fma2(A[r],  __double_as_longlong(v.x), Wp[2 * i]);
                fma2(Bc[r], __double_as_longlong(v.y), Wp[2 * i + 1]);
            }
        }

        // fold + shfl-reduce over dg (lane bits 2..4)
        float s[8];
        #pragma unroll
        for (int r = 0; r < 8; r++) {
            add2(A[r], Bc[r]);
            float lo, hi;
            unpack2(A[r], lo, hi);
            s[r] = lo + hi;
        }
        #pragma unroll
        for (int r = 0; r < 8; r++) {
            s[r] += __shfl_xor_sync(0xffffffffu, s[r], 4);
            s[r] += __shfl_xor_sync(0xffffffffu, s[r], 8);
            s[r] += __shfl_xor_sync(0xffffffffu, s[r], 16);
        }

        // this lane owns (row = dg, col = cg)
        float v = s[0];
        v = (dg == 1) ? s[1] : v;
        v = (dg == 2) ? s[2] : v;
        v = (dg == 3) ? s[3] : v;
        v = (dg == 4) ? s[4] : v;
        v = (dg == 5) ? s[5] : v;
        v = (dg == 6) ? s[6] : v;
        v = (dg == 7) ? s[7] : v;
        v += xu;

        const int wr = (t + 1 < Tsz);
        xu = xp[(size_t)(wr ? t + 1 : t) * Ksz];   // prefetch next step's xu
        hv = tanhf(v);

        if (wr) {
            const int pn = (t + 1) & 1;
            asm volatile("st.shared.f32 [%0], %1;" :: "r"(wrL[pn]), "f"(hv) : "memory");
            asm volatile("st.shared::cluster.f32 [%0], %1;" :: "r"(wrP[0][pn]), "f"(hv) : "memory");
            asm volatile("st.shared::cluster.f32 [%0], %1;" :: "r"(wrP[1][pn]), "f"(hv) : "memory");
            asm volatile("st.shared::cluster.f32 [%0], %1;" :: "r"(wrP[2][pn]), "f"(hv) : "memory");
        }
        // one full cluster barrier per step: orders all local+remote h stores
        // of step t before any step-t+1 read; also closes the double buffer.
        asm volatile("barrier.cluster.arrive.aligned;" ::: "memory");
        asm volatile("barrier.cluster.wait.aligned;"   ::: "memory");
    }

    out[(size_t)(b0 + dg) * Ksz + cg] = hv;
}

// ===========================================================================
// Launch
// ===========================================================================
extern "C" void kernel_launch(void* const* d_in, const int* in_sizes, int n_in,
                              void* d_out, int out_size)
{
    const float* x    = (const float*)d_in[0];   // [256, 512, 256]
    const float* U    = (const float*)d_in[1];   // [256, 256]
    const float* W    = (const float*)d_in[2];   // [256, 256]
    const float* bias = (const float*)d_in[3];   // [256]
    float* out        = (float*)d_out;           // [256, 1, 256]

    float* xU;
    cudaGetSymbolAddress((void**)&xU, g_xU);

    dim3 gridA(Ksz / 128, (Bsz * Tsz) / 128);    // (2, 1024)
    gemm_xu_tc<<<gridA, 256>>>(x, U, bias, xU);

    rnn_rec11_kernel<<<(Bsz / 8) * 4, 512>>>(xU, W, out);
}